// round 12
// baseline (speedup 1.0000x reference)
#include <cuda_runtime.h>

#define T_STEPS 8192
#define N_CH    4096
#define DT      0.01f
#define L       32                    // time steps per chunk (register tile / thread)
#define KCHUNKS (T_STEPS / L)         // 256
#define CPB     256                   // threads per block = channels per block
#define SLICES  (N_CH / CPB)          // 16
#define NBLK    (KCHUNKS * SLICES)    // 4096 blocks per launch
#define GENSH   12                    // log2(NBLK)
#define WIN     16                    // lookback window

// Scan state (no cudaMalloc -> __device__ globals). Never reset: flags are
// generation-tagged, so stale values from previous graph replays read "empty".
__device__ float    g_agg [KCHUNKS * N_CH];     // zero-start chunk aggregate
__device__ float    g_pref[KCHUNKS * N_CH];     // inclusive prefix (state at chunk end)
__device__ unsigned g_flag[KCHUNKS * SLICES];   // base+1=agg ready, base+2=pref ready
__device__ unsigned g_ticket;                   // monotone across launches

__device__ __forceinline__ float ldcg(const float* p) {
    float v; asm volatile("ld.global.cg.f32 %0, [%1];" : "=f"(v) : "l"(p)); return v;
}
__device__ __forceinline__ void stcg(float* p, float v) {
    asm volatile("st.global.cg.f32 [%0], %1;" :: "l"(p), "f"(v));
}
// Streaming store: out is never re-read.
__device__ __forceinline__ void stcs(float* p, float v) {
    asm volatile("st.global.cs.f32 [%0], %1;" :: "l"(p), "f"(v));
}

__global__ void __launch_bounds__(CPB, 4) scan_kernel(const float* __restrict__ x,
                                                      const float* __restrict__ tau,
                                                      const float* __restrict__ bias,
                                                      float* __restrict__ out) {
    __shared__ unsigned s_vid;
    __shared__ int      s_flag[WIN];
    const int tid = threadIdx.x;

    // Chunk-major ticket: every ticket-predecessor is resident-or-done, so
    // aggregates always get published -> lookback can never deadlock.
    if (tid == 0) s_vid = atomicAdd(&g_ticket, 1u);
    __syncthreads();
    const unsigned gvid = s_vid;
    const unsigned base = (gvid >> GENSH) * 2u;   // generation tag
    const int vid   = (int)(gvid & (NBLK - 1));
    const int k     = vid / SLICES;               // chunk index (time)
    const int slice = vid % SLICES;               // channel slice
    const int j     = slice * CPB + tid;          // my channel

    const float a = DT / fmaxf(tau[j], DT);
    const float c = 1.0f - a;
    float cl = c;
#pragma unroll
    for (int p = 0; p < 5; ++p) cl *= cl;         // c^32

    const float* xp = x + (size_t)k * L * N_CH + j;

    // ---- Phase 1: load tile into registers, build zero-start aggregate ----
    float v[L];
#pragma unroll
    for (int r = 0; r < L; ++r)
        v[r] = xp[(size_t)r * N_CH];

    float agg = 0.f;
#pragma unroll
    for (int r = 0; r < L; ++r)
        agg = fmaf(c, agg, a * v[r]);

    float s_in;
    if (k == 0) {
        s_in = v[0] / a * 0.f + x[j];             // s_0 = input[0, :] (x[j] == v[0] here)
        s_in = v[0];                               // chunk 0 row 0 IS input[0]
        stcg(&g_pref[j], fmaf(cl, s_in, agg));
        __syncthreads();
        if (tid == 0) { __threadfence(); atomicExch(&g_flag[slice], base + 2u); }
    } else {
        stcg(&g_agg[(size_t)k * N_CH + j], agg);  // publish agg (never blocks)
        __syncthreads();
        if (tid == 0) { __threadfence(); atomicExch(&g_flag[k * SLICES + slice], base + 1u); }

        // ---- windowed decoupled lookback ----
        float carry = 0.f, factor = 1.f;
        int kk = k - 1;
        bool done = false;
        while (!done) {
            if (tid < WIN) {
                const int idx = kk - tid;
                unsigned f = 0u;
                if (idx >= 0) f = *(volatile unsigned*)&g_flag[idx * SLICES + slice];
                s_flag[tid] = (f > base) ? (int)(f - base) : 0;   // 0 empty, 1 agg, 2 pref
            }
            __syncthreads();
            int cnt = 0, d = -1;
#pragma unroll
            for (int i = 0; i < WIN; ++i) {
                const int f = s_flag[i];
                if (f == 0) break;
                cnt = i + 1;
                if (f == 2) { d = i; break; }
            }
            __syncthreads();
            if (cnt > 0) {
                __threadfence();   // acquire: order value loads after flag observation
                for (int i = 0; i < cnt; ++i) {
                    const float val = (i == d) ? ldcg(&g_pref[(size_t)(kk - i) * N_CH + j])
                                               : ldcg(&g_agg [(size_t)(kk - i) * N_CH + j]);
                    carry = fmaf(factor, val, carry);
                    if (i == d) { done = true; break; }
                    factor *= cl;
                }
                kk -= cnt;
            }
        }
        s_in = carry;

        stcg(&g_pref[(size_t)k * N_CH + j], fmaf(cl, s_in, agg));
        __syncthreads();
        if (tid == 0) { __threadfence(); atomicExch(&g_flag[k * SLICES + slice], base + 2u); }
    }

    // ---- Phase 2: replay from register tile (NO global re-read), stream out ----
    const float b = bias[j];
    float s = s_in;
    float* op = out + (size_t)k * L * N_CH + j;
#pragma unroll
    for (int r = 0; r < L; ++r) {
        s = fmaf(c, s, a * v[r]);
        stcs(op + (size_t)r * N_CH, s + b);
    }
}

extern "C" void kernel_launch(void* const* d_in, const int* in_sizes, int n_in,
                              void* d_out, int out_size) {
    const float* x    = (const float*)d_in[0];   // [T, N]
    const float* tau  = (const float*)d_in[1];   // [N]
    const float* bias = (const float*)d_in[2];   // [N]
    float*       out  = (float*)d_out;           // [T*N]

    scan_kernel<<<NBLK, CPB>>>(x, tau, bias, out);
}

// round 13
// speedup vs baseline: 1.1680x; 1.1680x over previous
#include <cuda_runtime.h>

#define T_STEPS 8192
#define N_CH    4096
#define DT      0.01f
#define L       32                    // time steps per chunk (32 KB tile/CTA -> L2-resident)
#define KCHUNKS (T_STEPS / L)         // 256
#define CPB     256                   // threads per block = channels per block
#define SLICES  (N_CH / CPB)          // 16
#define NBLK    (KCHUNKS * SLICES)    // 4096 blocks per launch
#define GENSH   12                    // log2(NBLK)
#define WIN     16                    // lookback window

// Scan state (no cudaMalloc -> __device__ globals). Never reset: flags are
// generation-tagged, so stale values from previous graph replays read "empty".
__device__ float    g_agg [KCHUNKS * N_CH];     // zero-start chunk aggregate
__device__ float    g_pref[KCHUNKS * N_CH];     // inclusive prefix (state at chunk end)
__device__ unsigned g_flag[KCHUNKS * SLICES];   // base+1=agg ready, base+2=pref ready
__device__ unsigned g_ticket;                   // monotone across launches

__device__ __forceinline__ float ldcg(const float* p) {
    float v; asm volatile("ld.global.cg.f32 %0, [%1];" : "=f"(v) : "l"(p)); return v;
}
__device__ __forceinline__ void stcg(float* p, float v) {
    asm volatile("st.global.cg.f32 [%0], %1;" :: "l"(p), "f"(v));
}
// Streaming store: out is never re-read; keep it from evicting x tiles in L2.
__device__ __forceinline__ void stcs(float* p, float v) {
    asm volatile("st.global.cs.f32 [%0], %1;" :: "l"(p), "f"(v));
}

__global__ void __launch_bounds__(CPB) scan_kernel(const float* __restrict__ x,
                                                   const float* __restrict__ tau,
                                                   const float* __restrict__ bias,
                                                   float* __restrict__ out) {
    __shared__ unsigned s_vid;
    __shared__ int      s_flag[WIN];
    const int tid = threadIdx.x;

    // Chunk-major ticket: every ticket-predecessor is resident-or-done, so
    // aggregates always get published -> lookback can never deadlock.
    if (tid == 0) s_vid = atomicAdd(&g_ticket, 1u);
    __syncthreads();
    const unsigned gvid = s_vid;
    const unsigned base = (gvid >> GENSH) * 2u;   // generation tag
    const int vid   = (int)(gvid & (NBLK - 1));
    const int k     = vid / SLICES;               // chunk index (time)
    const int slice = vid % SLICES;               // channel slice
    const int j     = slice * CPB + tid;          // my channel

    const float a = DT / fmaxf(tau[j], DT);
    const float c = 1.0f - a;
    float cl = c;
#pragma unroll
    for (int p = 0; p < 5; ++p) cl *= cl;         // c^32

    const float* xp = x + (size_t)k * L * N_CH + j;

    // ---- Phase 1: zero-start aggregate over my 32 rows ----
    float agg = 0.f;
#pragma unroll 16
    for (int r = 0; r < L; ++r)
        agg = fmaf(c, agg, a * xp[(size_t)r * N_CH]);

    float s_in;
    if (k == 0) {
        s_in = x[j];                              // s_0 = input[0, :]
        stcg(&g_pref[j], fmaf(cl, s_in, agg));
        __syncthreads();
        if (tid == 0) { __threadfence(); atomicExch(&g_flag[slice], base + 2u); }
    } else {
        stcg(&g_agg[(size_t)k * N_CH + j], agg);  // publish agg (never blocks)
        __syncthreads();
        if (tid == 0) { __threadfence(); atomicExch(&g_flag[k * SLICES + slice], base + 1u); }

        // ---- windowed decoupled lookback ----
        float carry = 0.f, factor = 1.f;
        int kk = k - 1;
        bool done = false;
        while (!done) {
            if (tid < WIN) {
                const int idx = kk - tid;
                unsigned f = 0u;
                if (idx >= 0) f = *(volatile unsigned*)&g_flag[idx * SLICES + slice];
                s_flag[tid] = (f > base) ? (int)(f - base) : 0;   // 0 empty, 1 agg, 2 pref
            }
            __syncthreads();
            int cnt = 0, d = -1;
#pragma unroll
            for (int i = 0; i < WIN; ++i) {
                const int f = s_flag[i];
                if (f == 0) break;
                cnt = i + 1;
                if (f == 2) { d = i; break; }
            }
            __syncthreads();
            if (cnt > 0) {
                __threadfence();   // acquire: order value loads after flag observation
                for (int i = 0; i < cnt; ++i) {
                    const float v = (i == d) ? ldcg(&g_pref[(size_t)(kk - i) * N_CH + j])
                                             : ldcg(&g_agg [(size_t)(kk - i) * N_CH + j]);
                    carry = fmaf(factor, v, carry);
                    if (i == d) { done = true; break; }
                    factor *= cl;
                }
                kk -= cnt;
            }
        }
        s_in = carry;

        stcg(&g_pref[(size_t)k * N_CH + j], fmaf(cl, s_in, agg));
        __syncthreads();
        if (tid == 0) { __threadfence(); atomicExch(&g_flag[k * SLICES + slice], base + 2u); }
    }

    // ---- Phase 2: replay tile (re-read hits L2: 32 KB tile, ~37 MB resident set) ----
    const float b = bias[j];
    float s = s_in;
    float* op = out + (size_t)k * L * N_CH + j;
#pragma unroll 8
    for (int r = 0; r < L; ++r) {
        s = fmaf(c, s, a * xp[(size_t)r * N_CH]);
        stcs(op + (size_t)r * N_CH, s + b);
    }
}

extern "C" void kernel_launch(void* const* d_in, const int* in_sizes, int n_in,
                              void* d_out, int out_size) {
    const float* x    = (const float*)d_in[0];   // [T, N]
    const float* tau  = (const float*)d_in[1];   // [N]
    const float* bias = (const float*)d_in[2];   // [N]
    float*       out  = (float*)d_out;           // [T*N]

    scan_kernel<<<NBLK, CPB>>>(x, tau, bias, out);
}